// round 1
// baseline (speedup 1.0000x reference)
#include <cuda_runtime.h>
#include <math.h>

#define H  1024
#define B  64
#define L  1024
#define VP 32000
#define VC 32000
#define LSPLIT 16

// ---- scratch (device globals; no allocation allowed) ----
__device__ float g_hnew[B * H];
__device__ float g_scores[B * L];
__device__ float g_attn[B * L];
__device__ float g_ctxpart[B * LSPLIT * H];
__device__ float g_ctx[B * H];
__device__ float g_concat[B * H];

__device__ __forceinline__ float warp_sum(float v) {
#pragma unroll
    for (int o = 16; o; o >>= 1) v += __shfl_xor_sync(0xffffffffu, v, o);
    return v;
}

// ---------------------------------------------------------------------------
// 1) Fused GRU step: one block per hidden index i. Loads the 6 weight rows
//    (w_ih[i], w_ih[i+H], w_ih[i+2H], w_hh same) into smem once; 8 warps each
//    handle 8 batch rows. x = emb[seq[b]] gathered directly (L2-resident).
// ---------------------------------------------------------------------------
__global__ void gru_kernel(const int* __restrict__ seq,
                           const float* __restrict__ hprev,
                           const float* __restrict__ emb,
                           const float* __restrict__ w_ih,
                           const float* __restrict__ w_hh,
                           const float* __restrict__ b_ih,
                           const float* __restrict__ b_hh,
                           float* __restrict__ hidden_out) {
    int i = blockIdx.x;
    __shared__ float sw[6][H];
    for (int k = threadIdx.x; k < H; k += blockDim.x) {
        sw[0][k] = w_ih[(size_t)i * H + k];
        sw[1][k] = w_ih[(size_t)(i + H) * H + k];
        sw[2][k] = w_ih[(size_t)(i + 2 * H) * H + k];
        sw[3][k] = w_hh[(size_t)i * H + k];
        sw[4][k] = w_hh[(size_t)(i + H) * H + k];
        sw[5][k] = w_hh[(size_t)(i + 2 * H) * H + k];
    }
    __syncthreads();

    int wid = threadIdx.x >> 5, lane = threadIdx.x & 31;
#pragma unroll
    for (int t = 0; t < 8; t++) {
        int b = wid + 8 * t;
        const float* xr = emb + (size_t)seq[b] * H;
        const float* hr = hprev + (size_t)b * H;
        float sir = 0.f, siz = 0.f, sin_ = 0.f, shr = 0.f, shz = 0.f, shn = 0.f;
        for (int k = lane; k < H; k += 32) {
            float xv = xr[k], hv = hr[k];
            sir += xv * sw[0][k]; siz += xv * sw[1][k]; sin_ += xv * sw[2][k];
            shr += hv * sw[3][k]; shz += hv * sw[4][k]; shn += hv * sw[5][k];
        }
        sir = warp_sum(sir); siz = warp_sum(siz); sin_ = warp_sum(sin_);
        shr = warp_sum(shr); shz = warp_sum(shz); shn = warp_sum(shn);
        if (lane == 0) {
            float gr = sir + b_ih[i] + shr + b_hh[i];
            float gz = siz + b_ih[i + H] + shz + b_hh[i + H];
            float r = 1.f / (1.f + expf(-gr));
            float z = 1.f / (1.f + expf(-gz));
            float n = tanhf(sin_ + b_ih[i + 2 * H] + r * (shn + b_hh[i + 2 * H]));
            float hv = hprev[(size_t)b * H + i];
            float hn = (1.f - z) * n + z * hv;
            g_hnew[b * H + i] = hn;
            hidden_out[b * H + i] = hn;
        }
    }
}

// ---------------------------------------------------------------------------
// 2) scores[b][l] = h_new[b] . enc[l][b]   (one block per l; streams the
//    256KB enc[l] slab coalesced once from HBM, h_new hits L2)
// ---------------------------------------------------------------------------
__global__ void scores_kernel(const float* __restrict__ enc) {
    int l = blockIdx.x;
    int wid = threadIdx.x >> 5, lane = threadIdx.x & 31;
    const float* encl = enc + (size_t)l * B * H;
#pragma unroll
    for (int t = 0; t < 8; t++) {
        int b = wid + 8 * t;
        const float* er = encl + (size_t)b * H;
        const float* hr = g_hnew + b * H;
        float s = 0.f;
        for (int k = lane; k < H; k += 32) s += er[k] * hr[k];
        s = warp_sum(s);
        if (lane == 0) g_scores[b * L + l] = s;
    }
}

// ---------------------------------------------------------------------------
// 3) softmax over L per batch row; also writes attn output region
// ---------------------------------------------------------------------------
__global__ void softmax_kernel(float* __restrict__ attn_out) {
    int b = blockIdx.x, tid = threadIdx.x;
    __shared__ float sh[8];
    __shared__ float sval;

    float m = -1e30f;
    for (int l = tid; l < L; l += 256) m = fmaxf(m, g_scores[b * L + l]);
#pragma unroll
    for (int o = 16; o; o >>= 1) m = fmaxf(m, __shfl_xor_sync(0xffffffffu, m, o));
    if ((tid & 31) == 0) sh[tid >> 5] = m;
    __syncthreads();
    if (tid == 0) {
        float mm = sh[0];
        for (int j = 1; j < 8; j++) mm = fmaxf(mm, sh[j]);
        sval = mm;
    }
    __syncthreads();
    m = sval;

    float s = 0.f;
    for (int l = tid; l < L; l += 256) s += expf(g_scores[b * L + l] - m);
    s = warp_sum(s);
    __syncthreads();                 // protect sval before rewrite
    if ((tid & 31) == 0) sh[tid >> 5] = s;
    __syncthreads();
    if (tid == 0) {
        float ss = 0.f;
        for (int j = 0; j < 8; j++) ss += sh[j];
        sval = ss;
    }
    __syncthreads();
    float inv = 1.f / sval;

    for (int l = tid; l < L; l += 256) {
        float w = expf(g_scores[b * L + l] - m) * inv;
        g_attn[b * L + l] = w;
        attn_out[b * L + l] = w;
    }
}

// ---------------------------------------------------------------------------
// 4) context partials: grid (B, LSPLIT). Each block accumulates 64 l-slices
//    for one b; reads enc[l][b][:] coalesced (threads over h).
// ---------------------------------------------------------------------------
__global__ void ctx_part_kernel(const float* __restrict__ enc) {
    int b = blockIdx.x, c = blockIdx.y;
    int tid = threadIdx.x;
    float a0 = 0.f, a1 = 0.f, a2 = 0.f, a3 = 0.f;
    int l0 = c * (L / LSPLIT);
    for (int j = 0; j < L / LSPLIT; j++) {
        int l = l0 + j;
        float w = g_attn[b * L + l];
        const float* er = enc + (size_t)l * B * H + (size_t)b * H;
        a0 += w * er[tid];
        a1 += w * er[tid + 256];
        a2 += w * er[tid + 512];
        a3 += w * er[tid + 768];
    }
    float* p = g_ctxpart + ((size_t)(b * LSPLIT + c)) * H;
    p[tid] = a0; p[tid + 256] = a1; p[tid + 512] = a2; p[tid + 768] = a3;
}

__global__ void ctx_reduce_kernel() {
    int b = blockIdx.x, tid = threadIdx.x;
    for (int h = tid; h < H; h += 256) {
        float s = 0.f;
#pragma unroll
        for (int c = 0; c < LSPLIT; c++)
            s += g_ctxpart[((size_t)(b * LSPLIT + c)) * H + h];
        g_ctx[b * H + h] = s;
    }
}

// ---------------------------------------------------------------------------
// 5) concat_output = tanh([h_new|context] @ concat_w.T + concat_b)
//    one block per output index i; 2H-row (8KB) in smem.
// ---------------------------------------------------------------------------
__global__ void concat_kernel(const float* __restrict__ cw,
                              const float* __restrict__ cb) {
    int i = blockIdx.x;
    __shared__ float sw[2 * H];
    for (int k = threadIdx.x; k < 2 * H; k += blockDim.x)
        sw[k] = cw[(size_t)i * 2 * H + k];
    __syncthreads();
    int wid = threadIdx.x >> 5, lane = threadIdx.x & 31;
#pragma unroll
    for (int t = 0; t < 8; t++) {
        int b = wid + 8 * t;
        const float* hr = g_hnew + b * H;
        const float* cr = g_ctx + b * H;
        float s = 0.f;
        for (int k = lane; k < H; k += 32)
            s += hr[k] * sw[k] + cr[k] * sw[k + H];
        s = warp_sum(s);
        if (lane == 0) g_concat[b * H + i] = tanhf(s + cb[i]);
    }
}

// ---------------------------------------------------------------------------
// 6) vocab logits for both heads: grid = VP+VC blocks, one weight row each.
// ---------------------------------------------------------------------------
__global__ void logits_kernel(const float* __restrict__ wp,
                              const float* __restrict__ bp,
                              const float* __restrict__ wc,
                              const float* __restrict__ bc,
                              float* __restrict__ out) {
    int v = blockIdx.x;
    const float* wrow;
    float bias;
    float* obase;
    int vout;
    if (v < VP) {
        wrow = wp + (size_t)v * H; bias = bp[v];
        obase = out; vout = v;
    } else {
        int u = v - VP;
        wrow = wc + (size_t)u * H; bias = bc[u];
        obase = out + (size_t)B * VP; vout = u;
    }
    __shared__ float sw[H];
    for (int k = threadIdx.x; k < H; k += blockDim.x) sw[k] = wrow[k];
    __syncthreads();
    int wid = threadIdx.x >> 5, lane = threadIdx.x & 31;
#pragma unroll
    for (int t = 0; t < 8; t++) {
        int b = wid + 8 * t;
        const float* cr = g_concat + b * H;
        float s = 0.f;
        for (int k = lane; k < H; k += 32) s += cr[k] * sw[k];
        s = warp_sum(s);
        if (lane == 0) obase[(size_t)b * VP + vout] = s + bias;
    }
}

// ---------------------------------------------------------------------------
extern "C" void kernel_launch(void* const* d_in, const int* in_sizes, int n_in,
                              void* d_out, int out_size) {
    const int*   seq         = (const int*)d_in[0];
    const float* last_hidden = (const float*)d_in[1];
    const float* enc         = (const float*)d_in[2];
    const float* emb         = (const float*)d_in[3];
    const float* w_ih        = (const float*)d_in[4];
    const float* w_hh        = (const float*)d_in[5];
    const float* b_ih        = (const float*)d_in[6];
    const float* b_hh        = (const float*)d_in[7];
    const float* concat_w    = (const float*)d_in[8];
    const float* concat_b    = (const float*)d_in[9];
    const float* owp         = (const float*)d_in[10];
    const float* obp         = (const float*)d_in[11];
    const float* owc         = (const float*)d_in[12];
    const float* obc         = (const float*)d_in[13];

    float* out        = (float*)d_out;
    float* out_hidden = out + (size_t)B * (VP + VC);   // [1,B,H]
    float* out_attn   = out_hidden + (size_t)B * H;    // [B,1,L]

    gru_kernel<<<H, 256>>>(seq, last_hidden, emb, w_ih, w_hh, b_ih, b_hh, out_hidden);
    scores_kernel<<<L, 256>>>(enc);
    softmax_kernel<<<B, 256>>>(out_attn);
    ctx_part_kernel<<<dim3(B, LSPLIT), 256>>>(enc);
    ctx_reduce_kernel<<<B, 256>>>();
    concat_kernel<<<H, 256>>>(concat_w, concat_b);
    logits_kernel<<<VP + VC, 256>>>(owp, obp, owc, obc, out);
}

// round 2
// speedup vs baseline: 2.7270x; 2.7270x over previous
#include <cuda_runtime.h>
#include <math.h>

#define H  1024
#define B  64
#define L  1024
#define VP 32000
#define VC 32000
#define LSPLIT 16
#define KC 32
#define TV 128

typedef unsigned long long ull;

// ---- scratch (device globals; no allocation allowed) ----
__device__ __align__(16) float g_hnew[B * H];
__device__ __align__(16) float g_scores[B * L];
__device__ __align__(16) float g_attn[B * L];
__device__ __align__(16) float g_ctxpart[B * LSPLIT * H];
__device__ __align__(16) float g_ctx[B * H];
__device__ __align__(16) float g_concatT[H * B];   // [k][b], feeds logits GEMM

__device__ __forceinline__ float warp_sum(float v) {
#pragma unroll
    for (int o = 16; o; o >>= 1) v += __shfl_xor_sync(0xffffffffu, v, o);
    return v;
}

__device__ __forceinline__ ull pack2(float a, float b) {
    ull r; asm("mov.b64 %0, {%1,%2};" : "=l"(r) : "f"(a), "f"(b)); return r;
}
__device__ __forceinline__ void unpack2(ull v, float& a, float& b) {
    asm("mov.b64 {%0,%1}, %2;" : "=f"(a), "=f"(b) : "l"(v));
}
__device__ __forceinline__ ull fma2(ull a, ull b, ull c) {
    ull d; asm("fma.rn.f32x2 %0, %1, %2, %3;" : "=l"(d) : "l"(a), "l"(b), "l"(c));
    return d;
}

// ---------------------------------------------------------------------------
// 1) Fused GRU step: one block per hidden index i.
// ---------------------------------------------------------------------------
__global__ void gru_kernel(const int* __restrict__ seq,
                           const float* __restrict__ hprev,
                           const float* __restrict__ emb,
                           const float* __restrict__ w_ih,
                           const float* __restrict__ w_hh,
                           const float* __restrict__ b_ih,
                           const float* __restrict__ b_hh,
                           float* __restrict__ hidden_out) {
    int i = blockIdx.x;
    __shared__ float sw[6][H];
    for (int k = threadIdx.x; k < H; k += blockDim.x) {
        sw[0][k] = w_ih[(size_t)i * H + k];
        sw[1][k] = w_ih[(size_t)(i + H) * H + k];
        sw[2][k] = w_ih[(size_t)(i + 2 * H) * H + k];
        sw[3][k] = w_hh[(size_t)i * H + k];
        sw[4][k] = w_hh[(size_t)(i + H) * H + k];
        sw[5][k] = w_hh[(size_t)(i + 2 * H) * H + k];
    }
    __syncthreads();

    int wid = threadIdx.x >> 5, lane = threadIdx.x & 31;
#pragma unroll
    for (int t = 0; t < 8; t++) {
        int b = wid + 8 * t;
        const float* xr = emb + (size_t)seq[b] * H;
        const float* hr = hprev + (size_t)b * H;
        float sir = 0.f, siz = 0.f, sin_ = 0.f, shr = 0.f, shz = 0.f, shn = 0.f;
        for (int k = lane; k < H; k += 32) {
            float xv = xr[k], hv = hr[k];
            sir += xv * sw[0][k]; siz += xv * sw[1][k]; sin_ += xv * sw[2][k];
            shr += hv * sw[3][k]; shz += hv * sw[4][k]; shn += hv * sw[5][k];
        }
        sir = warp_sum(sir); siz = warp_sum(siz); sin_ = warp_sum(sin_);
        shr = warp_sum(shr); shz = warp_sum(shz); shn = warp_sum(shn);
        if (lane == 0) {
            float gr = sir + b_ih[i] + shr + b_hh[i];
            float gz = siz + b_ih[i + H] + shz + b_hh[i + H];
            float r = 1.f / (1.f + expf(-gr));
            float z = 1.f / (1.f + expf(-gz));
            float n = tanhf(sin_ + b_ih[i + 2 * H] + r * (shn + b_hh[i + 2 * H]));
            float hv = hprev[(size_t)b * H + i];
            float hn = (1.f - z) * n + z * hv;
            g_hnew[b * H + i] = hn;
            hidden_out[b * H + i] = hn;
        }
    }
}

// ---------------------------------------------------------------------------
// 2) scores[b][l] = h_new[b] . enc[l][b]  (float4 vectorized)
// ---------------------------------------------------------------------------
__global__ void scores_kernel(const float* __restrict__ enc) {
    int l = blockIdx.x;
    int wid = threadIdx.x >> 5, lane = threadIdx.x & 31;
    const float4* encl = (const float4*)(enc + (size_t)l * B * H);
#pragma unroll
    for (int t = 0; t < 8; t++) {
        int b = wid + 8 * t;
        const float4* er = encl + (size_t)b * (H / 4);
        const float4* hr = (const float4*)g_hnew + (size_t)b * (H / 4);
        float s = 0.f;
        for (int k = lane; k < H / 4; k += 32) {
            float4 e = er[k], h = hr[k];
            s += e.x * h.x + e.y * h.y + e.z * h.z + e.w * h.w;
        }
        s = warp_sum(s);
        if (lane == 0) g_scores[b * L + l] = s;
    }
}

// ---------------------------------------------------------------------------
// 3) softmax over L per batch row; also writes attn output region
// ---------------------------------------------------------------------------
__global__ void softmax_kernel(float* __restrict__ attn_out) {
    int b = blockIdx.x, tid = threadIdx.x;
    __shared__ float sh[8];
    __shared__ float sval;

    float m = -1e30f;
    for (int l = tid; l < L; l += 256) m = fmaxf(m, g_scores[b * L + l]);
#pragma unroll
    for (int o = 16; o; o >>= 1) m = fmaxf(m, __shfl_xor_sync(0xffffffffu, m, o));
    if ((tid & 31) == 0) sh[tid >> 5] = m;
    __syncthreads();
    if (tid == 0) {
        float mm = sh[0];
        for (int j = 1; j < 8; j++) mm = fmaxf(mm, sh[j]);
        sval = mm;
    }
    __syncthreads();
    m = sval;

    float s = 0.f;
    for (int l = tid; l < L; l += 256) s += expf(g_scores[b * L + l] - m);
    s = warp_sum(s);
    __syncthreads();
    if ((tid & 31) == 0) sh[tid >> 5] = s;
    __syncthreads();
    if (tid == 0) {
        float ss = 0.f;
        for (int j = 0; j < 8; j++) ss += sh[j];
        sval = ss;
    }
    __syncthreads();
    float inv = 1.f / sval;

    for (int l = tid; l < L; l += 256) {
        float w = expf(g_scores[b * L + l] - m) * inv;
        g_attn[b * L + l] = w;
        attn_out[b * L + l] = w;
    }
}

// ---------------------------------------------------------------------------
// 4) context partials (float4): grid (B, LSPLIT)
// ---------------------------------------------------------------------------
__global__ void ctx_part_kernel(const float* __restrict__ enc) {
    int b = blockIdx.x, c = blockIdx.y;
    int tid = threadIdx.x;
    float4 a = make_float4(0.f, 0.f, 0.f, 0.f);
    int l0 = c * (L / LSPLIT);
    for (int j = 0; j < L / LSPLIT; j++) {
        int l = l0 + j;
        float w = g_attn[b * L + l];
        float4 e = ((const float4*)(enc + (size_t)l * B * H + (size_t)b * H))[tid];
        a.x += w * e.x; a.y += w * e.y; a.z += w * e.z; a.w += w * e.w;
    }
    ((float4*)(g_ctxpart + ((size_t)(b * LSPLIT + c)) * H))[tid] = a;
}

__global__ void ctx_reduce_kernel() {
    int b = blockIdx.x, tid = threadIdx.x;   // 256 threads, one float4 each
    float4 s = make_float4(0.f, 0.f, 0.f, 0.f);
#pragma unroll
    for (int c = 0; c < LSPLIT; c++) {
        float4 p = ((const float4*)(g_ctxpart + ((size_t)(b * LSPLIT + c)) * H))[tid];
        s.x += p.x; s.y += p.y; s.z += p.z; s.w += p.w;
    }
    ((float4*)(g_ctx + (size_t)b * H))[tid] = s;
}

// ---------------------------------------------------------------------------
// 5) concat_output = tanh([h_new|context] @ concat_w.T + concat_b)
//    writes TRANSPOSED g_concatT[i][b] for the logits GEMM.
// ---------------------------------------------------------------------------
__global__ void concat_kernel(const float* __restrict__ cw,
                              const float* __restrict__ cb) {
    int i = blockIdx.x;
    __shared__ float sw[2 * H];
    for (int k = threadIdx.x; k < 2 * H; k += blockDim.x)
        sw[k] = cw[(size_t)i * 2 * H + k];
    __syncthreads();
    int wid = threadIdx.x >> 5, lane = threadIdx.x & 31;
#pragma unroll
    for (int t = 0; t < 8; t++) {
        int b = wid + 8 * t;
        const float* hr = g_hnew + b * H;
        const float* cr = g_ctx + b * H;
        float s = 0.f;
        for (int k = lane; k < H; k += 32)
            s += hr[k] * sw[k] + cr[k] * sw[k + H];
        s = warp_sum(s);
        if (lane == 0) g_concatT[(size_t)i * B + b] = tanhf(s + cb[i]);
    }
}

// ---------------------------------------------------------------------------
// 6) vocab logits: register-tiled SGEMM with packed f32x2 FMA.
//    Block = 128 vocab rows x 64 batch; 256 threads (16 b-groups x 16 v-groups);
//    per-thread 8v x 4b held as 16 packed f32x2 accumulators.
// ---------------------------------------------------------------------------
__global__ __launch_bounds__(256) void logits_gemm(
        const float* __restrict__ wp, const float* __restrict__ bp,
        const float* __restrict__ wc, const float* __restrict__ bc,
        float* __restrict__ out) {
    int v0 = blockIdx.x * TV;
    const float* W; const float* bias; float* obase;
    if (v0 < VP) { W = wp; bias = bp; obase = out; }
    else { W = wc; bias = bc; obase = out + (size_t)B * VP; v0 -= VP; }

    __shared__ float Wt[KC][TV + 4];   // k-major, padded
    __shared__ float Xt[KC][B];

    int t = threadIdx.x;
    int tx = t & 15;          // b-group: b = tx*4 .. tx*4+3
    int ty = t >> 4;          // v-group: v = ty*8 .. ty*8+7

    ull acc[4][4];
#pragma unroll
    for (int i = 0; i < 4; i++)
#pragma unroll
        for (int j = 0; j < 4; j++) acc[i][j] = 0ull;

    for (int kc = 0; kc < H; kc += KC) {
        // W tile: 128 rows x 32 k, transpose into smem (k-major)
#pragma unroll
        for (int r = 0; r < 4; r++) {
            int f = t + r * 256;       // float4 id 0..1023
            int v = f >> 3;            // 0..127
            int kq = f & 7;            // float4 within the 32-k row
            float4 w4 = *(const float4*)(W + (size_t)(v0 + v) * H + kc + kq * 4);
            Wt[kq * 4 + 0][v] = w4.x;
            Wt[kq * 4 + 1][v] = w4.y;
            Wt[kq * 4 + 2][v] = w4.z;
            Wt[kq * 4 + 3][v] = w4.w;
        }
        // X tile: contiguous copy from g_concatT
#pragma unroll
        for (int r = 0; r < 2; r++) {
            int f = t + r * 256;       // float4 id 0..511
            int k = f >> 4; int b4 = f & 15;
            *(float4*)&Xt[k][b4 * 4] =
                *(const float4*)(g_concatT + (size_t)(kc + k) * B + b4 * 4);
        }
        __syncthreads();

#pragma unroll 4
        for (int k = 0; k < KC; k++) {
            ulonglong2 wl = *(const ulonglong2*)&Wt[k][ty * 8];      // v pairs (0,1),(2,3)
            ulonglong2 wh = *(const ulonglong2*)&Wt[k][ty * 8 + 4];  // v pairs (4,5),(6,7)
            float4 xv = *(const float4*)&Xt[k][tx * 4];
            ull xb0 = pack2(xv.x, xv.x);
            ull xb1 = pack2(xv.y, xv.y);
            ull xb2 = pack2(xv.z, xv.z);
            ull xb3 = pack2(xv.w, xv.w);
            acc[0][0] = fma2(wl.x, xb0, acc[0][0]);
            acc[0][1] = fma2(wl.x, xb1, acc[0][1]);
            acc[0][2] = fma2(wl.x, xb2, acc[0][2]);
            acc[0][3] = fma2(wl.x, xb3, acc[0][3]);
            acc[1][0] = fma2(wl.y, xb0, acc[1][0]);
            acc[1][1] = fma2(wl.y, xb1, acc[1][1]);
            acc[1][2] = fma2(wl.y, xb2, acc[1][2]);
            acc[1][3] = fma2(wl.y, xb3, acc[1][3]);
            acc[2][0] = fma2(wh.x, xb0, acc[2][0]);
            acc[2][1] = fma2(wh.x, xb1, acc[2][1]);
            acc[2][2] = fma2(wh.x, xb2, acc[2][2]);
            acc[2][3] = fma2(wh.x, xb3, acc[2][3]);
            acc[3][0] = fma2(wh.y, xb0, acc[3][0]);
            acc[3][1] = fma2(wh.y, xb1, acc[3][1]);
            acc[3][2] = fma2(wh.y, xb2, acc[3][2]);
            acc[3][3] = fma2(wh.y, xb3, acc[3][3]);
        }
        __syncthreads();
    }

    // epilogue: out[b][v] (+bias), float2 stores over consecutive v
#pragma unroll
    for (int vi2 = 0; vi2 < 4; vi2++) {
        int gv = v0 + ty * 8 + vi2 * 2;
        float b0 = bias[gv], b1 = bias[gv + 1];
#pragma unroll
        for (int bj = 0; bj < 4; bj++) {
            int b = tx * 4 + bj;
            float lo, hi; unpack2(acc[vi2][bj], lo, hi);
            float2 r2 = make_float2(lo + b0, hi + b1);
            *(float2*)(obase + (size_t)b * VP + gv) = r2;
        }
    }
}

// ---------------------------------------------------------------------------
extern "C" void kernel_launch(void* const* d_in, const int* in_sizes, int n_in,
                              void* d_out, int out_size) {
    const int*   seq         = (const int*)d_in[0];
    const float* last_hidden = (const float*)d_in[1];
    const float* enc         = (const float*)d_in[2];
    const float* emb         = (const float*)d_in[3];
    const float* w_ih        = (const float*)d_in[4];
    const float* w_hh        = (const float*)d_in[5];
    const float* b_ih        = (const float*)d_in[6];
    const float* b_hh        = (const float*)d_in[7];
    const float* concat_w    = (const float*)d_in[8];
    const float* concat_b    = (const float*)d_in[9];
    const float* owp         = (const float*)d_in[10];
    const float* obp         = (const float*)d_in[11];
    const float* owc         = (const float*)d_in[12];
    const float* obc         = (const float*)d_in[13];

    float* out        = (float*)d_out;
    float* out_hidden = out + (size_t)B * (VP + VC);   // [1,B,H]
    float* out_attn   = out_hidden + (size_t)B * H;    // [B,1,L]

    gru_kernel<<<H, 256>>>(seq, last_hidden, emb, w_ih, w_hh, b_ih, b_hh, out_hidden);
    scores_kernel<<<L, 256>>>(enc);
    softmax_kernel<<<B, 256>>>(out_attn);
    ctx_part_kernel<<<dim3(B, LSPLIT), 256>>>(enc);
    ctx_reduce_kernel<<<B, 256>>>();
    concat_kernel<<<H, 256>>>(concat_w, concat_b);
    logits_gemm<<<(VP + VC) / TV, 256>>>(owp, obp, owc, obc, out);
}